// round 1
// baseline (speedup 1.0000x reference)
#include <cuda_runtime.h>
#include <math.h>

// Problem dims
#define NN 512
#define TT 64
#define CC 64
#define HH 4
#define HD 16
#define MM (NN*TT)      // 32768 rows
#define FEC 256
#define EPS 1e-5f

// ---------------------------------------------------------------------------
// Scratch: one big __device__ array (no allocations allowed).
// ---------------------------------------------------------------------------
#define SZ 2097152          // MM*CC = T*H*N*HD
#define OFF_QH   0
#define OFF_KH   (1*SZ)
#define OFF_VH   (2*SZ)
#define OFF_ATT  (3*SZ)
#define OFF_Z1   (4*SZ)
#define OFF_X    (5*SZ)
#define OFF_H    (6*SZ)     // size 4*SZ
#define OFF_Z2   (10*SZ)
#define OFF_OUT1 (11*SZ)
#define OFF_T1   (12*SZ)
#define OFF_T2   (13*SZ)
#define OFF_T3   (14*SZ)
#define OFF_OUT2 (15*SZ)
#define OFF_ZA   (16*SZ)
#define OFF_ZB   (17*SZ)
#define OFF_ADJN (18*SZ)              // 262144
#define OFF_PART (18*SZ + 262144)     // 1024
#define OFF_STAT (18*SZ + 262144 + 1024)
#define SCRATCH_TOTAL (18*SZ + 262144 + 1024 + 16)

__device__ float g_scratch[SCRATCH_TOTAL];

// ---------------------------------------------------------------------------
// adj InstanceNorm: row-partial reduction -> final stats -> normalize
// ---------------------------------------------------------------------------
__global__ void adj_rowred_kernel(const float* __restrict__ adj, float* __restrict__ part) {
    __shared__ float s1[256], s2[256];
    int r = blockIdx.x, t = threadIdx.x;
    float a = adj[r * 512 + t];
    float b = adj[r * 512 + 256 + t];
    s1[t] = a + b;
    s2[t] = a * a + b * b;
    __syncthreads();
    for (int st = 128; st > 0; st >>= 1) {
        if (t < st) { s1[t] += s1[t + st]; s2[t] += s2[t + st]; }
        __syncthreads();
    }
    if (t == 0) { part[r] = s1[0]; part[512 + r] = s2[0]; }
}

__global__ void adj_final_kernel(const float* __restrict__ part, float* __restrict__ stats) {
    __shared__ float s1[256], s2[256];
    int t = threadIdx.x;
    s1[t] = part[t] + part[t + 256];
    s2[t] = part[512 + t] + part[512 + t + 256];
    __syncthreads();
    for (int st = 128; st > 0; st >>= 1) {
        if (t < st) { s1[t] += s1[t + st]; s2[t] += s2[t + st]; }
        __syncthreads();
    }
    if (t == 0) {
        float mean = s1[0] * (1.0f / 262144.0f);
        float var  = s2[0] * (1.0f / 262144.0f) - mean * mean;
        stats[0] = mean;
        stats[1] = rsqrtf(var + EPS);
    }
}

__global__ void adj_norm_kernel(const float* __restrict__ adj, const float* __restrict__ stats,
                                float* __restrict__ adjn) {
    int i = blockIdx.x * 512 + threadIdx.x;
    adjn[i] = (adj[i] - stats[0]) * stats[1];
}

// ---------------------------------------------------------------------------
// Per-head projections q/k/v. Output layout [T,H,N,HD].
// blockDim=256 (4 rows of (n,t) per block).
// ---------------------------------------------------------------------------
__global__ void proj_kernel(const float* __restrict__ q, const float* __restrict__ k,
                            const float* __restrict__ v,
                            const float* __restrict__ Wq, const float* __restrict__ Wk,
                            const float* __restrict__ Wv,
                            float* __restrict__ qh, float* __restrict__ kh,
                            float* __restrict__ vh) {
    __shared__ float wq[256], wk[256], wv[256];
    __shared__ float rq[4][64], rk[4][64], rv[4][64];
    int tid = threadIdx.x;
    wq[tid] = Wq[tid];
    wk[tid] = Wk[tid];
    wv[tid] = Wv[tid];
    int g = tid >> 6, c = tid & 63;
    int row = blockIdx.x * 4 + g;
    rq[g][c] = q[row * 64 + c];
    rk[g][c] = k[row * 64 + c];
    rv[g][c] = v[row * 64 + c];
    __syncthreads();
    int hh = c >> 4, d = c & 15;
    float sq = 0.f, sk = 0.f, sv = 0.f;
#pragma unroll
    for (int e = 0; e < 16; e++) {
        sq += rq[g][hh * 16 + e] * wq[d * 16 + e];
        sk += rk[g][hh * 16 + e] * wk[d * 16 + e];
        sv += rv[g][hh * 16 + e] * wv[d * 16 + e];
    }
    int n = row / TT, t = row % TT;
    int o = ((t * HH + hh) * NN + n) * HD + d;
    qh[o] = sq; kh[o] = sk; vh[o] = sv;
}

// ---------------------------------------------------------------------------
// Node-attention, one (t,h) per CTA, one q-row per thread, online softmax.
// blockDim=512, dyn smem = 64KB (K and V tiles [512,16] each).
// Output into [N,T,C] layout (heads recombined).
// ---------------------------------------------------------------------------
__global__ void attn_kernel(const float* __restrict__ qh, const float* __restrict__ kh,
                            const float* __restrict__ vh, float* __restrict__ attn) {
    extern __shared__ float sm[];
    float* Ks = sm;
    float* Vs = sm + NN * HD;
    int th = blockIdx.x;
    int t = th >> 2, h = th & 3;
    int base = th * NN * HD;
    for (int i = threadIdx.x; i < NN * HD; i += blockDim.x) {
        Ks[i] = kh[base + i];
        Vs[i] = vh[base + i];
    }
    __syncthreads();

    int qi = threadIdx.x;
    const float SCL = 0.125f * 1.44269504088896f;  // 1/sqrt(C) * log2(e)
    float qr[HD];
#pragma unroll
    for (int d = 0; d < HD; d++) qr[d] = qh[base + qi * HD + d] * SCL;

    float m = -INFINITY, l = 0.f, acc[HD];
#pragma unroll
    for (int d = 0; d < HD; d++) acc[d] = 0.f;

    for (int k = 0; k < NN; k++) {
        float s = 0.f;
#pragma unroll
        for (int d = 0; d < HD; d++) s += qr[d] * Ks[k * HD + d];
        if (s <= m) {
            float p = exp2f(s - m);
            l += p;
#pragma unroll
            for (int d = 0; d < HD; d++) acc[d] += p * Vs[k * HD + d];
        } else {
            float corr = exp2f(m - s);
            l = l * corr + 1.f;
#pragma unroll
            for (int d = 0; d < HD; d++) acc[d] = acc[d] * corr + Vs[k * HD + d];
            m = s;
        }
    }
    float inv = 1.f / l;
    int o = (qi * TT + t) * CC + h * HD;
#pragma unroll
    for (int d = 0; d < HD; d++) attn[o + d] = acc[d] * inv;
}

// ---------------------------------------------------------------------------
// Y[M,Ncols] = X[M,K] @ W[Ncols,K]^T (+bias, +residual, +relu).
// Tile 64x64, blockDim=256, 4x4 microtiles.
// ---------------------------------------------------------------------------
template <bool RELU, bool HASB, bool HASR>
__global__ void gemm_xt_kernel(const float* __restrict__ X, const float* __restrict__ W,
                               const float* __restrict__ bias, const float* __restrict__ R,
                               float* __restrict__ Y, int K, int Ncols) {
    __shared__ float Xs[64][65];
    __shared__ float Ws[64][65];
    int tid = threadIdx.x;
    int tx = tid & 15, ty = tid >> 4;
    int rowBase = blockIdx.y * 64, colBase = blockIdx.x * 64;
    float acc[4][4];
#pragma unroll
    for (int i = 0; i < 4; i++)
#pragma unroll
        for (int j = 0; j < 4; j++) acc[i][j] = 0.f;

    for (int k0 = 0; k0 < K; k0 += 64) {
#pragma unroll
        for (int it = 0; it < 16; it++) {
            int idx = tid + it * 256;
            int i = idx >> 6, j = idx & 63;
            Xs[i][j] = X[(rowBase + i) * K + k0 + j];
            Ws[i][j] = W[(colBase + i) * K + k0 + j];
        }
        __syncthreads();
#pragma unroll 8
        for (int e = 0; e < 64; e++) {
            float a0 = Xs[ty][e], a1 = Xs[ty + 16][e], a2 = Xs[ty + 32][e], a3 = Xs[ty + 48][e];
            float b0 = Ws[tx][e], b1 = Ws[tx + 16][e], b2 = Ws[tx + 32][e], b3 = Ws[tx + 48][e];
            acc[0][0] += a0 * b0; acc[0][1] += a0 * b1; acc[0][2] += a0 * b2; acc[0][3] += a0 * b3;
            acc[1][0] += a1 * b0; acc[1][1] += a1 * b1; acc[1][2] += a1 * b2; acc[1][3] += a1 * b3;
            acc[2][0] += a2 * b0; acc[2][1] += a2 * b1; acc[2][2] += a2 * b2; acc[2][3] += a2 * b3;
            acc[3][0] += a3 * b0; acc[3][1] += a3 * b1; acc[3][2] += a3 * b2; acc[3][3] += a3 * b3;
        }
        __syncthreads();
    }
#pragma unroll
    for (int i = 0; i < 4; i++) {
        int r = rowBase + ty + 16 * i;
#pragma unroll
        for (int j = 0; j < 4; j++) {
            int c = colBase + tx + 16 * j;
            float v = acc[i][j];
            if (HASB) v += bias[c];
            if (HASR) v += R[r * Ncols + c];
            if (RELU) v = fmaxf(v, 0.f);
            Y[r * Ncols + c] = v;
        }
    }
}

// ---------------------------------------------------------------------------
// GCN spatial: Y[512,4096] = A[512,512] @ X[512,4096] (+bias[col%64], +relu)
// ---------------------------------------------------------------------------
template <bool RELU>
__global__ void gcn_spatial_kernel(const float* __restrict__ A, const float* __restrict__ X,
                                   const float* __restrict__ bias, float* __restrict__ Y) {
    __shared__ float As[64][65];
    __shared__ float Xs[64][65];
    int tid = threadIdx.x;
    int tx = tid & 15, ty = tid >> 4;
    int rowBase = blockIdx.y * 64, colBase = blockIdx.x * 64;
    float acc[4][4];
#pragma unroll
    for (int i = 0; i < 4; i++)
#pragma unroll
        for (int j = 0; j < 4; j++) acc[i][j] = 0.f;

    for (int k0 = 0; k0 < 512; k0 += 64) {
#pragma unroll
        for (int it = 0; it < 16; it++) {
            int idx = tid + it * 256;
            int i = idx >> 6, j = idx & 63;
            As[i][j] = A[(rowBase + i) * 512 + k0 + j];
            Xs[i][j] = X[(k0 + i) * 4096 + colBase + j];
        }
        __syncthreads();
#pragma unroll 8
        for (int e = 0; e < 64; e++) {
            float a0 = As[ty][e], a1 = As[ty + 16][e], a2 = As[ty + 32][e], a3 = As[ty + 48][e];
            float b0 = Xs[e][tx], b1 = Xs[e][tx + 16], b2 = Xs[e][tx + 32], b3 = Xs[e][tx + 48];
            acc[0][0] += a0 * b0; acc[0][1] += a0 * b1; acc[0][2] += a0 * b2; acc[0][3] += a0 * b3;
            acc[1][0] += a1 * b0; acc[1][1] += a1 * b1; acc[1][2] += a1 * b2; acc[1][3] += a1 * b3;
            acc[2][0] += a2 * b0; acc[2][1] += a2 * b1; acc[2][2] += a2 * b2; acc[2][3] += a2 * b3;
            acc[3][0] += a3 * b0; acc[3][1] += a3 * b1; acc[3][2] += a3 * b2; acc[3][3] += a3 * b3;
        }
        __syncthreads();
    }
#pragma unroll
    for (int i = 0; i < 4; i++) {
        int r = rowBase + ty + 16 * i;
#pragma unroll
        for (int j = 0; j < 4; j++) {
            int c = colBase + tx + 16 * j;
            float v = acc[i][j] + bias[c & 63];
            if (RELU) v = fmaxf(v, 0.f);
            Y[r * 4096 + c] = v;
        }
    }
}

// ---------------------------------------------------------------------------
// LayerNorm over last dim (64). 4 rows per 256-thread block.
// ---------------------------------------------------------------------------
__global__ void ln_kernel(const float* __restrict__ Z, const float* __restrict__ gamma,
                          const float* __restrict__ beta, float* __restrict__ Y) {
    __shared__ float red1[4][2];
    __shared__ float red2[4][2];
    int tid = threadIdx.x;
    int g = tid >> 6, c = tid & 63;
    int row = blockIdx.x * 4 + g;
    float v = Z[row * 64 + c];
    float s = v;
#pragma unroll
    for (int o = 16; o > 0; o >>= 1) s += __shfl_xor_sync(0xffffffff, s, o);
    int wig = c >> 5;
    if ((c & 31) == 0) red1[g][wig] = s;
    __syncthreads();
    float mean = (red1[g][0] + red1[g][1]) * (1.f / 64.f);
    float d = v - mean;
    float s2 = d * d;
#pragma unroll
    for (int o = 16; o > 0; o >>= 1) s2 += __shfl_xor_sync(0xffffffff, s2, o);
    if ((c & 31) == 0) red2[g][wig] = s2;
    __syncthreads();
    float var = (red2[g][0] + red2[g][1]) * (1.f / 64.f);
    Y[row * 64 + c] = d * rsqrtf(var + EPS) * gamma[c] + beta[c];
}

// ---------------------------------------------------------------------------
// Gated fusion: out = sig(za+zb)*o1 + (1-sig)*o2
// ---------------------------------------------------------------------------
__global__ void gate_kernel(const float* __restrict__ za, const float* __restrict__ zb,
                            const float* __restrict__ o1, const float* __restrict__ o2,
                            float* __restrict__ out) {
    int i = blockIdx.x * 256 + threadIdx.x;
    float x = za[i] + zb[i];
    float s = 1.f / (1.f + __expf(-x));
    out[i] = s * o1[i] + (1.f - s) * o2[i];
}

// ---------------------------------------------------------------------------
extern "C" void kernel_launch(void* const* d_in, const int* in_sizes, int n_in,
                              void* d_out, int out_size) {
    const float* value = (const float*)d_in[0];
    const float* key_t = (const float*)d_in[1];
    const float* query = (const float*)d_in[2];
    const float* adj   = (const float*)d_in[3];
    const float* Wv    = (const float*)d_in[4];
    const float* Wk    = (const float*)d_in[5];
    const float* Wq    = (const float*)d_in[6];
    const float* Wo    = (const float*)d_in[7];
    const float* bo    = (const float*)d_in[8];
    const float* g1    = (const float*)d_in[9];
    const float* b1    = (const float*)d_in[10];
    const float* g2    = (const float*)d_in[11];
    const float* b2    = (const float*)d_in[12];
    const float* Wf1   = (const float*)d_in[13];
    const float* bf1   = (const float*)d_in[14];
    const float* Wf2   = (const float*)d_in[15];
    const float* bf2   = (const float*)d_in[16];
    const float* Wg1   = (const float*)d_in[17];
    const float* bg1   = (const float*)d_in[18];
    const float* Wg2   = (const float*)d_in[19];
    const float* bg2   = (const float*)d_in[20];
    const float* Wo1   = (const float*)d_in[21];
    const float* bo1   = (const float*)d_in[22];
    const float* Wo2   = (const float*)d_in[23];
    const float* bo2   = (const float*)d_in[24];
    float* out = (float*)d_out;

    float* base;
    cudaGetSymbolAddress((void**)&base, g_scratch);
    float* qh   = base + OFF_QH;
    float* kh   = base + OFF_KH;
    float* vh   = base + OFF_VH;
    float* attn = base + OFF_ATT;
    float* z1   = base + OFF_Z1;
    float* x    = base + OFF_X;
    float* hbuf = base + OFF_H;
    float* z2   = base + OFF_Z2;
    float* out1 = base + OFF_OUT1;
    float* t1   = base + OFF_T1;
    float* t2   = base + OFF_T2;
    float* t3   = base + OFF_T3;
    float* out2 = base + OFF_OUT2;
    float* za   = base + OFF_ZA;
    float* zb   = base + OFF_ZB;
    float* adjn = base + OFF_ADJN;
    float* part = base + OFF_PART;
    float* stat = base + OFF_STAT;

    // adj InstanceNorm
    adj_rowred_kernel<<<512, 256>>>(adj, part);
    adj_final_kernel<<<1, 256>>>(part, stat);
    adj_norm_kernel<<<512, 512>>>(adj, stat, adjn);

    // head projections
    proj_kernel<<<MM / 4, 256>>>(query, key_t, value, Wq, Wk, Wv, qh, kh, vh);

    // node-attention (flash, per (t,h))
    cudaFuncSetAttribute(attn_kernel, cudaFuncAttributeMaxDynamicSharedMemorySize, 65536);
    attn_kernel<<<TT * HH, 512, 65536>>>(qh, kh, vh, attn);

    // Wo projection + bias + residual(query), then LN1 -> x
    gemm_xt_kernel<false, true, true><<<dim3(1, MM / 64), 256>>>(attn, Wo, bo, query, z1, 64, 64);
    ln_kernel<<<MM / 4, 256>>>(z1, g1, b1, x);

    // FFN: h = relu(x@Wf1^T+bf1);  z2 = h@Wf2^T+bf2 + x; out1 = LN2(z2)
    gemm_xt_kernel<true, true, false><<<dim3(4, MM / 64), 256>>>(x, Wf1, bf1, nullptr, hbuf, 64, 256);
    gemm_xt_kernel<false, true, true><<<dim3(1, MM / 64), 256>>>(hbuf, Wf2, bf2, x, z2, 256, 64);
    ln_kernel<<<MM / 4, 256>>>(z2, g2, b2, out1);

    // GCN: t1 = query@Wg1^T; t2 = relu(adjn@t1 + bg1); t3 = t2@Wg2^T; out2 = adjn@t3 + bg2
    gemm_xt_kernel<false, false, false><<<dim3(1, MM / 64), 256>>>(query, Wg1, nullptr, nullptr, t1, 64, 64);
    gcn_spatial_kernel<true><<<dim3(64, 8), 256>>>(adjn, t1, bg1, t2);
    gemm_xt_kernel<false, false, false><<<dim3(1, MM / 64), 256>>>(t2, Wg2, nullptr, nullptr, t3, 64, 64);
    gcn_spatial_kernel<false><<<dim3(64, 8), 256>>>(adjn, t3, bg2, out2);

    // gating
    gemm_xt_kernel<false, true, false><<<dim3(1, MM / 64), 256>>>(out1, Wo1, bo1, nullptr, za, 64, 64);
    gemm_xt_kernel<false, true, false><<<dim3(1, MM / 64), 256>>>(out2, Wo2, bo2, nullptr, zb, 64, 64);
    gate_kernel<<<MM * CC / 256, 256>>>(za, zb, out1, out2, out);
}

// round 2
// speedup vs baseline: 1.0040x; 1.0040x over previous
#include <cuda_runtime.h>
#include <math.h>

// Problem dims
#define NN 512
#define TT 64
#define CC 64
#define HH 4
#define HD 16
#define MM (NN*TT)      // 32768 rows
#define FEC 256
#define EPS 1e-5f

// ---------------------------------------------------------------------------
// Scratch: one big __device__ array (no allocations allowed).
// ---------------------------------------------------------------------------
#define SZ 2097152          // MM*CC = T*H*N*HD
#define OFF_QH   0
#define OFF_KH   (1*SZ)
#define OFF_VH   (2*SZ)
#define OFF_ATT  (3*SZ)
#define OFF_Z1   (4*SZ)
#define OFF_X    (5*SZ)
#define OFF_H    (6*SZ)     // size 4*SZ
#define OFF_Z2   (10*SZ)
#define OFF_OUT1 (11*SZ)
#define OFF_T1   (12*SZ)
#define OFF_T2   (13*SZ)
#define OFF_T3   (14*SZ)
#define OFF_OUT2 (15*SZ)
#define OFF_ZA   (16*SZ)
#define OFF_ZB   (17*SZ)
#define OFF_ADJN (18*SZ)              // 262144
#define OFF_PART (18*SZ + 262144)     // 1024
#define OFF_STAT (18*SZ + 262144 + 1024)
#define SCRATCH_TOTAL (18*SZ + 262144 + 1024 + 16)

__device__ float g_scratch[SCRATCH_TOTAL];

// ---------------------------------------------------------------------------
// adj InstanceNorm: row-partial reduction -> final stats -> normalize
// ---------------------------------------------------------------------------
__global__ void adj_rowred_kernel(const float* __restrict__ adj, float* __restrict__ part) {
    __shared__ float s1[256], s2[256];
    int r = blockIdx.x, t = threadIdx.x;
    float a = adj[r * 512 + t];
    float b = adj[r * 512 + 256 + t];
    s1[t] = a + b;
    s2[t] = a * a + b * b;
    __syncthreads();
    for (int st = 128; st > 0; st >>= 1) {
        if (t < st) { s1[t] += s1[t + st]; s2[t] += s2[t + st]; }
        __syncthreads();
    }
    if (t == 0) { part[r] = s1[0]; part[512 + r] = s2[0]; }
}

__global__ void adj_final_kernel(const float* __restrict__ part, float* __restrict__ stats) {
    __shared__ float s1[256], s2[256];
    int t = threadIdx.x;
    s1[t] = part[t] + part[t + 256];
    s2[t] = part[512 + t] + part[512 + t + 256];
    __syncthreads();
    for (int st = 128; st > 0; st >>= 1) {
        if (t < st) { s1[t] += s1[t + st]; s2[t] += s2[t + st]; }
        __syncthreads();
    }
    if (t == 0) {
        float mean = s1[0] * (1.0f / 262144.0f);
        float var  = s2[0] * (1.0f / 262144.0f) - mean * mean;
        stats[0] = mean;
        stats[1] = rsqrtf(var + EPS);
    }
}

__global__ void adj_norm_kernel(const float* __restrict__ adj, const float* __restrict__ stats,
                                float* __restrict__ adjn) {
    int i = blockIdx.x * 512 + threadIdx.x;
    adjn[i] = (adj[i] - stats[0]) * stats[1];
}

// ---------------------------------------------------------------------------
// Per-head projections q/k/v. Output layout [T,H,N,HD].
// blockDim=256 (4 rows of (n,t) per block).
// ---------------------------------------------------------------------------
__global__ void proj_kernel(const float* __restrict__ q, const float* __restrict__ k,
                            const float* __restrict__ v,
                            const float* __restrict__ Wq, const float* __restrict__ Wk,
                            const float* __restrict__ Wv,
                            float* __restrict__ qh, float* __restrict__ kh,
                            float* __restrict__ vh) {
    __shared__ float wq[256], wk[256], wv[256];
    __shared__ float rq[4][64], rk[4][64], rv[4][64];
    int tid = threadIdx.x;
    wq[tid] = Wq[tid];
    wk[tid] = Wk[tid];
    wv[tid] = Wv[tid];
    int g = tid >> 6, c = tid & 63;
    int row = blockIdx.x * 4 + g;
    rq[g][c] = q[row * 64 + c];
    rk[g][c] = k[row * 64 + c];
    rv[g][c] = v[row * 64 + c];
    __syncthreads();
    int hh = c >> 4, d = c & 15;
    float sq = 0.f, sk = 0.f, sv = 0.f;
#pragma unroll
    for (int e = 0; e < 16; e++) {
        sq += rq[g][hh * 16 + e] * wq[d * 16 + e];
        sk += rk[g][hh * 16 + e] * wk[d * 16 + e];
        sv += rv[g][hh * 16 + e] * wv[d * 16 + e];
    }
    int n = row / TT, t = row % TT;
    int o = ((t * HH + hh) * NN + n) * HD + d;
    qh[o] = sq; kh[o] = sk; vh[o] = sv;
}

// ---------------------------------------------------------------------------
// Node-attention, one (t,h) per CTA, one q-row per thread, online softmax.
// blockDim=512, dyn smem = 64KB (K and V tiles [512,16] each).
// Output into [N,T,C] layout (heads recombined).
// ---------------------------------------------------------------------------
__global__ void attn_kernel(const float* __restrict__ qh, const float* __restrict__ kh,
                            const float* __restrict__ vh, float* __restrict__ attn) {
    extern __shared__ float sm[];
    float* Ks = sm;
    float* Vs = sm + NN * HD;
    int th = blockIdx.x;
    int t = th >> 2, h = th & 3;
    int base = th * NN * HD;
    for (int i = threadIdx.x; i < NN * HD; i += blockDim.x) {
        Ks[i] = kh[base + i];
        Vs[i] = vh[base + i];
    }
    __syncthreads();

    int qi = threadIdx.x;
    const float SCL = 0.125f * 1.44269504088896f;  // 1/sqrt(C) * log2(e)
    float qr[HD];
#pragma unroll
    for (int d = 0; d < HD; d++) qr[d] = qh[base + qi * HD + d] * SCL;

    float m = -INFINITY, l = 0.f, acc[HD];
#pragma unroll
    for (int d = 0; d < HD; d++) acc[d] = 0.f;

    for (int k = 0; k < NN; k++) {
        float s = 0.f;
#pragma unroll
        for (int d = 0; d < HD; d++) s += qr[d] * Ks[k * HD + d];
        if (s <= m) {
            float p = exp2f(s - m);
            l += p;
#pragma unroll
            for (int d = 0; d < HD; d++) acc[d] += p * Vs[k * HD + d];
        } else {
            float corr = exp2f(m - s);
            l = l * corr + 1.f;
#pragma unroll
            for (int d = 0; d < HD; d++) acc[d] = acc[d] * corr + Vs[k * HD + d];
            m = s;
        }
    }
    float inv = 1.f / l;
    int o = (qi * TT + t) * CC + h * HD;
#pragma unroll
    for (int d = 0; d < HD; d++) attn[o + d] = acc[d] * inv;
}

// ---------------------------------------------------------------------------
// Y[M,Ncols] = X[M,K] @ W[Ncols,K]^T (+bias, +residual, +relu).
// Tile 64x64, blockDim=256, 4x4 microtiles.
// ---------------------------------------------------------------------------
template <bool RELU, bool HASB, bool HASR>
__global__ void gemm_xt_kernel(const float* __restrict__ X, const float* __restrict__ W,
                               const float* __restrict__ bias, const float* __restrict__ R,
                               float* __restrict__ Y, int K, int Ncols) {
    __shared__ float Xs[64][65];
    __shared__ float Ws[64][65];
    int tid = threadIdx.x;
    int tx = tid & 15, ty = tid >> 4;
    int rowBase = blockIdx.y * 64, colBase = blockIdx.x * 64;
    float acc[4][4];
#pragma unroll
    for (int i = 0; i < 4; i++)
#pragma unroll
        for (int j = 0; j < 4; j++) acc[i][j] = 0.f;

    for (int k0 = 0; k0 < K; k0 += 64) {
#pragma unroll
        for (int it = 0; it < 16; it++) {
            int idx = tid + it * 256;
            int i = idx >> 6, j = idx & 63;
            Xs[i][j] = X[(rowBase + i) * K + k0 + j];
            Ws[i][j] = W[(colBase + i) * K + k0 + j];
        }
        __syncthreads();
#pragma unroll 8
        for (int e = 0; e < 64; e++) {
            float a0 = Xs[ty][e], a1 = Xs[ty + 16][e], a2 = Xs[ty + 32][e], a3 = Xs[ty + 48][e];
            float b0 = Ws[tx][e], b1 = Ws[tx + 16][e], b2 = Ws[tx + 32][e], b3 = Ws[tx + 48][e];
            acc[0][0] += a0 * b0; acc[0][1] += a0 * b1; acc[0][2] += a0 * b2; acc[0][3] += a0 * b3;
            acc[1][0] += a1 * b0; acc[1][1] += a1 * b1; acc[1][2] += a1 * b2; acc[1][3] += a1 * b3;
            acc[2][0] += a2 * b0; acc[2][1] += a2 * b1; acc[2][2] += a2 * b2; acc[2][3] += a2 * b3;
            acc[3][0] += a3 * b0; acc[3][1] += a3 * b1; acc[3][2] += a3 * b2; acc[3][3] += a3 * b3;
        }
        __syncthreads();
    }
#pragma unroll
    for (int i = 0; i < 4; i++) {
        int r = rowBase + ty + 16 * i;
#pragma unroll
        for (int j = 0; j < 4; j++) {
            int c = colBase + tx + 16 * j;
            float v = acc[i][j];
            if (HASB) v += bias[c];
            if (HASR) v += R[r * Ncols + c];
            if (RELU) v = fmaxf(v, 0.f);
            Y[r * Ncols + c] = v;
        }
    }
}

// ---------------------------------------------------------------------------
// GCN spatial: Y[512,4096] = A[512,512] @ X[512,4096] (+bias[col%64], +relu)
// ---------------------------------------------------------------------------
template <bool RELU>
__global__ void gcn_spatial_kernel(const float* __restrict__ A, const float* __restrict__ X,
                                   const float* __restrict__ bias, float* __restrict__ Y) {
    __shared__ float As[64][65];
    __shared__ float Xs[64][65];
    int tid = threadIdx.x;
    int tx = tid & 15, ty = tid >> 4;
    int rowBase = blockIdx.y * 64, colBase = blockIdx.x * 64;
    float acc[4][4];
#pragma unroll
    for (int i = 0; i < 4; i++)
#pragma unroll
        for (int j = 0; j < 4; j++) acc[i][j] = 0.f;

    for (int k0 = 0; k0 < 512; k0 += 64) {
#pragma unroll
        for (int it = 0; it < 16; it++) {
            int idx = tid + it * 256;
            int i = idx >> 6, j = idx & 63;
            As[i][j] = A[(rowBase + i) * 512 + k0 + j];
            Xs[i][j] = X[(k0 + i) * 4096 + colBase + j];
        }
        __syncthreads();
#pragma unroll 8
        for (int e = 0; e < 64; e++) {
            float a0 = As[ty][e], a1 = As[ty + 16][e], a2 = As[ty + 32][e], a3 = As[ty + 48][e];
            float b0 = Xs[e][tx], b1 = Xs[e][tx + 16], b2 = Xs[e][tx + 32], b3 = Xs[e][tx + 48];
            acc[0][0] += a0 * b0; acc[0][1] += a0 * b1; acc[0][2] += a0 * b2; acc[0][3] += a0 * b3;
            acc[1][0] += a1 * b0; acc[1][1] += a1 * b1; acc[1][2] += a1 * b2; acc[1][3] += a1 * b3;
            acc[2][0] += a2 * b0; acc[2][1] += a2 * b1; acc[2][2] += a2 * b2; acc[2][3] += a2 * b3;
            acc[3][0] += a3 * b0; acc[3][1] += a3 * b1; acc[3][2] += a3 * b2; acc[3][3] += a3 * b3;
        }
        __syncthreads();
    }
#pragma unroll
    for (int i = 0; i < 4; i++) {
        int r = rowBase + ty + 16 * i;
#pragma unroll
        for (int j = 0; j < 4; j++) {
            int c = colBase + tx + 16 * j;
            float v = acc[i][j] + bias[c & 63];
            if (RELU) v = fmaxf(v, 0.f);
            Y[r * 4096 + c] = v;
        }
    }
}

// ---------------------------------------------------------------------------
// LayerNorm over last dim (64). 4 rows per 256-thread block.
// ---------------------------------------------------------------------------
__global__ void ln_kernel(const float* __restrict__ Z, const float* __restrict__ gamma,
                          const float* __restrict__ beta, float* __restrict__ Y) {
    __shared__ float red1[4][2];
    __shared__ float red2[4][2];
    int tid = threadIdx.x;
    int g = tid >> 6, c = tid & 63;
    int row = blockIdx.x * 4 + g;
    float v = Z[row * 64 + c];
    float s = v;
#pragma unroll
    for (int o = 16; o > 0; o >>= 1) s += __shfl_xor_sync(0xffffffff, s, o);
    int wig = c >> 5;
    if ((c & 31) == 0) red1[g][wig] = s;
    __syncthreads();
    float mean = (red1[g][0] + red1[g][1]) * (1.f / 64.f);
    float d = v - mean;
    float s2 = d * d;
#pragma unroll
    for (int o = 16; o > 0; o >>= 1) s2 += __shfl_xor_sync(0xffffffff, s2, o);
    if ((c & 31) == 0) red2[g][wig] = s2;
    __syncthreads();
    float var = (red2[g][0] + red2[g][1]) * (1.f / 64.f);
    Y[row * 64 + c] = d * rsqrtf(var + EPS) * gamma[c] + beta[c];
}

// ---------------------------------------------------------------------------
// Gated fusion: out = sig(za+zb)*o1 + (1-sig)*o2
// ---------------------------------------------------------------------------
__global__ void gate_kernel(const float* __restrict__ za, const float* __restrict__ zb,
                            const float* __restrict__ o1, const float* __restrict__ o2,
                            float* __restrict__ out) {
    int i = blockIdx.x * 256 + threadIdx.x;
    float x = za[i] + zb[i];
    float s = 1.f / (1.f + __expf(-x));
    out[i] = s * o1[i] + (1.f - s) * o2[i];
}

// ---------------------------------------------------------------------------
extern "C" void kernel_launch(void* const* d_in, const int* in_sizes, int n_in,
                              void* d_out, int out_size) {
    const float* value = (const float*)d_in[0];
    const float* key_t = (const float*)d_in[1];
    const float* query = (const float*)d_in[2];
    const float* adj   = (const float*)d_in[3];
    const float* Wv    = (const float*)d_in[4];
    const float* Wk    = (const float*)d_in[5];
    const float* Wq    = (const float*)d_in[6];
    const float* Wo    = (const float*)d_in[7];
    const float* bo    = (const float*)d_in[8];
    const float* g1    = (const float*)d_in[9];
    const float* b1    = (const float*)d_in[10];
    const float* g2    = (const float*)d_in[11];
    const float* b2    = (const float*)d_in[12];
    const float* Wf1   = (const float*)d_in[13];
    const float* bf1   = (const float*)d_in[14];
    const float* Wf2   = (const float*)d_in[15];
    const float* bf2   = (const float*)d_in[16];
    const float* Wg1   = (const float*)d_in[17];
    const float* bg1   = (const float*)d_in[18];
    const float* Wg2   = (const float*)d_in[19];
    const float* bg2   = (const float*)d_in[20];
    const float* Wo1   = (const float*)d_in[21];
    const float* bo1   = (const float*)d_in[22];
    const float* Wo2   = (const float*)d_in[23];
    const float* bo2   = (const float*)d_in[24];
    float* out = (float*)d_out;

    float* base;
    cudaGetSymbolAddress((void**)&base, g_scratch);
    float* qh   = base + OFF_QH;
    float* kh   = base + OFF_KH;
    float* vh   = base + OFF_VH;
    float* attn = base + OFF_ATT;
    float* z1   = base + OFF_Z1;
    float* x    = base + OFF_X;
    float* hbuf = base + OFF_H;
    float* z2   = base + OFF_Z2;
    float* out1 = base + OFF_OUT1;
    float* t1   = base + OFF_T1;
    float* t2   = base + OFF_T2;
    float* t3   = base + OFF_T3;
    float* out2 = base + OFF_OUT2;
    float* za   = base + OFF_ZA;
    float* zb   = base + OFF_ZB;
    float* adjn = base + OFF_ADJN;
    float* part = base + OFF_PART;
    float* stat = base + OFF_STAT;

    // adj InstanceNorm
    adj_rowred_kernel<<<512, 256>>>(adj, part);
    adj_final_kernel<<<1, 256>>>(part, stat);
    adj_norm_kernel<<<512, 512>>>(adj, stat, adjn);

    // head projections
    proj_kernel<<<MM / 4, 256>>>(query, key_t, value, Wq, Wk, Wv, qh, kh, vh);

    // node-attention (flash, per (t,h))
    cudaFuncSetAttribute(attn_kernel, cudaFuncAttributeMaxDynamicSharedMemorySize, 65536);
    attn_kernel<<<TT * HH, 512, 65536>>>(qh, kh, vh, attn);

    // Wo projection + bias + residual(query), then LN1 -> x
    gemm_xt_kernel<false, true, true><<<dim3(1, MM / 64), 256>>>(attn, Wo, bo, query, z1, 64, 64);
    ln_kernel<<<MM / 4, 256>>>(z1, g1, b1, x);

    // FFN: h = relu(x@Wf1^T+bf1);  z2 = h@Wf2^T+bf2 + x; out1 = LN2(z2)
    gemm_xt_kernel<true, true, false><<<dim3(4, MM / 64), 256>>>(x, Wf1, bf1, nullptr, hbuf, 64, 256);
    gemm_xt_kernel<false, true, true><<<dim3(1, MM / 64), 256>>>(hbuf, Wf2, bf2, x, z2, 256, 64);
    ln_kernel<<<MM / 4, 256>>>(z2, g2, b2, out1);

    // GCN: t1 = query@Wg1^T; t2 = relu(adjn@t1 + bg1); t3 = t2@Wg2^T; out2 = adjn@t3 + bg2
    gemm_xt_kernel<false, false, false><<<dim3(1, MM / 64), 256>>>(query, Wg1, nullptr, nullptr, t1, 64, 64);
    gcn_spatial_kernel<true><<<dim3(64, 8), 256>>>(adjn, t1, bg1, t2);
    gemm_xt_kernel<false, false, false><<<dim3(1, MM / 64), 256>>>(t2, Wg2, nullptr, nullptr, t3, 64, 64);
    gcn_spatial_kernel<false><<<dim3(64, 8), 256>>>(adjn, t3, bg2, out2);

    // gating
    gemm_xt_kernel<false, true, false><<<dim3(1, MM / 64), 256>>>(out1, Wo1, bo1, nullptr, za, 64, 64);
    gemm_xt_kernel<false, true, false><<<dim3(1, MM / 64), 256>>>(out2, Wo2, bo2, nullptr, zb, 64, 64);
    gate_kernel<<<MM * CC / 256, 256>>>(za, zb, out1, out2, out);
}